// round 9
// baseline (speedup 1.0000x reference)
#include <cuda_runtime.h>
#include <cuda_fp16.h>
#include <cstdint>
#include <math.h>

#define B_  64
#define R_  32
#define H_  1024
#define IN_ 2048
#define M_  (B_*R_)
#define KSL 8                 // score k-slices
#define KCH (H_/KSL)          // 128 k per slice

// ---------------- scratch (__device__ globals) -----------------------------
__device__ __align__(16) __half g_Ehf[2][M_][H_];          // embeds fp16
__device__ __align__(16) __half g_Xf[2][M_][IN_];          // A fp16 [M,K]
__device__ __align__(16) __half g_Wf[4][H_][IN_];          // B fp16 [N,K] (W^T)
__device__ __align__(16) float  g_spart[KSL][B_][R_][R_];  // partial scores
__device__ __align__(16) float  g_npart[KSL][B_][R_][R_];  // partial norms

// ---------------- helpers --------------------------------------------------
__device__ __forceinline__ uint32_t smem_u32(const void* p){
    uint32_t a;
    asm("{ .reg .u64 t; cvta.to.shared.u64 t, %1; cvt.u32.u64 %0, t; }" : "=r"(a) : "l"(p));
    return a;
}
__device__ __forceinline__ void cpasync16(uint32_t dst, const void* src){
    asm volatile("cp.async.cg.shared.global [%0], [%1], 16;" :: "r"(dst), "l"(src));
}
#define CP_COMMIT() asm volatile("cp.async.commit_group;" ::: "memory")

#define LDSM_X4(d0,d1,d2,d3,addr) \
    asm volatile("ldmatrix.sync.aligned.m8n8.x4.shared.b16 {%0,%1,%2,%3}, [%4];" \
        : "=r"(d0),"=r"(d1),"=r"(d2),"=r"(d3) : "r"(addr))

#define MMA16816(c, a, b) \
    asm volatile("mma.sync.aligned.m16n8k16.row.col.f32.f16.f16.f32 " \
        "{%0,%1,%2,%3}, {%4,%5,%6,%7}, {%8,%9}, {%0,%1,%2,%3};" \
        : "+f"((c)[0]),"+f"((c)[1]),"+f"((c)[2]),"+f"((c)[3]) \
        : "r"((a)[0]),"r"((a)[1]),"r"((a)[2]),"r"((a)[3]), "r"((b)[0]),"r"((b)[1]))

__device__ __forceinline__ uint32_t sqr_h2(uint32_t x){
    __half2 h = *reinterpret_cast<__half2*>(&x);
    __half2 r = __hmul2(h, h);
    return *reinterpret_cast<uint32_t*>(&r);
}

// ---------------------------------------------------------------------------
// fused conv: part 1 (X fp32->fp16), part 2 (W transpose fp32->fp16 [N,K])
// grid 6144: [0,4096) convX, [4096,6144) convW
// ---------------------------------------------------------------------------
__global__ __launch_bounds__(256)
void conv_fused_kernel(const float* __restrict__ hist, const float* __restrict__ ques,
                       const float* __restrict__ W0, const float* __restrict__ W1,
                       const float* __restrict__ W2, const float* __restrict__ W3)
{
    const int bx = blockIdx.x;
    const int tid = threadIdx.x;
    if (bx < 4096){
        const int z = bx >> 11;
        const int xb = bx & 2047;
        const float* X = z ? ques : hist;
        __half* dst = &g_Xf[z][0][0];
        size_t i = ((size_t)xb * 256 + tid) * 8;
        float4 v0 = *(const float4*)(X + i);
        float4 v1 = *(const float4*)(X + i + 4);
        __half2 h[4];
        h[0] = __floats2half2_rn(v0.x, v0.y);
        h[1] = __floats2half2_rn(v0.z, v0.w);
        h[2] = __floats2half2_rn(v1.x, v1.y);
        h[3] = __floats2half2_rn(v1.z, v1.w);
        *(uint4*)(dst + i) = *(uint4*)h;
    } else {
        const float* Ws[4] = {W0, W1, W2, W3};
        const int wb  = bx - 4096;
        const int br  = wb >> 9;
        const int rem = wb & 511;
        const int n0  = (rem >> 5) * 64;
        const int k0  = (rem & 31) * 64;
        const float* W = Ws[br];
        __shared__ float s[64][65];
        #pragma unroll
        for (int i = 0; i < 4; i++){
            int idx = tid + i * 256;
            int r = idx >> 4;
            int c = (idx & 15) * 4;
            float4 v = *(const float4*)(W + (size_t)(k0 + r) * H_ + n0 + c);
            s[r][c] = v.x; s[r][c+1] = v.y; s[r][c+2] = v.z; s[r][c+3] = v.w;
        }
        __syncthreads();
        int nl  = tid >> 2;
        int seg = (tid & 3) * 16;
        __half2 h[8];
        #pragma unroll
        for (int j = 0; j < 8; j++)
            h[j] = __floats2half2_rn(s[seg + 2*j][nl], s[seg + 2*j + 1][nl]);
        __half* o = &g_Wf[br][n0 + nl][k0 + seg];
        *(uint4*)(o)     = *(uint4*)&h[0];
        *(uint4*)(o + 8) = *(uint4*)&h[4];
    }
}

// ---------------------------------------------------------------------------
// embed GEMM: HMMA m16n8k16 fp16, dual-branch, 3-stage cp.async, BK=64.
// CTA: BM=128, BN=32/branch -> grid (16, 32, 2) = 1024 CTAs (tail ~1.5%).
// 8 warps (4m x 2n): warp tile m32 x n16 per branch.
// ---------------------------------------------------------------------------
#define PITCH  72
#define ST_A   (128 * PITCH * 2)          // 18432
#define ST_Bb  (32 * PITCH * 2)           // 4608 per branch
#define ST_TOT (ST_A + 2 * ST_Bb)         // 27648 per stage
#define EMB_SMEM (3 * ST_TOT)             // 82944

__global__ __launch_bounds__(256, 2)
void embed_hmma_kernel(const float* __restrict__ bhy, const float* __restrict__ bhg,
                       const float* __restrict__ bqy, const float* __restrict__ bqg)
{
    extern __shared__ __align__(16) char sm[];
    const uint32_t smu = smem_u32(sm);

    const int tid  = threadIdx.x;
    const int lane = tid & 31, wid = tid >> 5;
    const int wm = wid >> 1, wn = wid & 1;
    const int z  = blockIdx.z;
    const int m0 = blockIdx.x * 128;
    const int n0 = blockIdx.y * 32;

    const __half* Xf = &g_Xf[z][0][0];
    const __half* Wy = &g_Wf[2*z + 0][0][0];
    const __half* Wg = &g_Wf[2*z + 1][0][0];

    float acc[2][2][2][4];
    #pragma unroll
    for (int b = 0; b < 2; b++)
        #pragma unroll
        for (int mi = 0; mi < 2; mi++)
            #pragma unroll
            for (int ni = 0; ni < 2; ni++)
                #pragma unroll
                for (int r = 0; r < 4; r++) acc[b][mi][ni][r] = 0.f;

    auto load_stage = [&](int s){
        const int k0 = s * 64, buf = s % 3;
        const uint32_t base = smu + buf * ST_TOT;
        #pragma unroll
        for (int i = 0; i < 4; i++){               // A: 1024 x 16B
            int idx = tid + i * 256;
            int row = idx >> 3, seg = idx & 7;
            cpasync16(base + (row * PITCH + seg * 8) * 2,
                      Xf + (size_t)(m0 + row) * IN_ + k0 + seg * 8);
        }
        #pragma unroll
        for (int i = 0; i < 2; i++){               // B: 512 x 16B (2 br x 32 r x 8)
            int idx = tid + i * 256;
            int t = idx >> 8, r = (idx >> 3) & 31, seg = idx & 7;
            const __half* W = t ? Wg : Wy;
            cpasync16(base + ST_A + t * ST_Bb + (r * PITCH + seg * 8) * 2,
                      W + (size_t)(n0 + r) * IN_ + k0 + seg * 8);
        }
    };

    load_stage(0); CP_COMMIT();
    load_stage(1); CP_COMMIT();

    const int lr = lane & 15;
    const int lc = (lane >> 4) * 8;

    for (int s = 0; s < 32; s++){
        if (s + 2 < 32) load_stage(s + 2);
        CP_COMMIT();
        asm volatile("cp.async.wait_group 2;" ::: "memory");
        __syncthreads();

        const uint32_t base  = smu + (s % 3) * ST_TOT;
        const uint32_t bBase = base + ST_A;

        #pragma unroll
        for (int kk = 0; kk < 64; kk += 16){
            uint32_t a[2][4];
            #pragma unroll
            for (int mi = 0; mi < 2; mi++){
                uint32_t ad = base + ((wm*32 + mi*16 + lr) * PITCH + kk + lc) * 2;
                LDSM_X4(a[mi][0], a[mi][1], a[mi][2], a[mi][3], ad);
            }
            #pragma unroll
            for (int br = 0; br < 2; br++){
                uint32_t t0, t1, t2, t3;
                uint32_t bd = bBase + br * ST_Bb +
                              ((wn*16 + lr) * PITCH + kk + lc) * 2;
                LDSM_X4(t0, t1, t2, t3, bd);
                uint32_t b0[2] = {t0, t2};
                uint32_t b1[2] = {t1, t3};
                #pragma unroll
                for (int mi = 0; mi < 2; mi++){
                    MMA16816(acc[br][mi][0], a[mi], b0);
                    MMA16816(acc[br][mi][1], a[mi], b1);
                }
            }
        }
        __syncthreads();
    }

    const float* by = z ? bqy : bhy;
    const float* bg = z ? bqg : bhg;
    const int grp = lane >> 2, tig = lane & 3;
    #pragma unroll
    for (int mi = 0; mi < 2; mi++){
        #pragma unroll
        for (int ni = 0; ni < 2; ni++){
            const float* ay = acc[0][mi][ni];
            const float* ag = acc[1][mi][ni];
            const int gn  = n0 + wn*16 + ni*8 + tig*2;
            const int gm0 = m0 + wm*32 + mi*16 + grp;
            const float by0 = by[gn], by1 = by[gn+1];
            const float bg0 = bg[gn], bg1 = bg[gn+1];
            float g0 = ag[0] + bg0; g0 = g0 > 0.f ? g0 : 0.01f * g0;
            float g1 = ag[1] + bg1; g1 = g1 > 0.f ? g1 : 0.01f * g1;
            float g2 = ag[2] + bg0; g2 = g2 > 0.f ? g2 : 0.01f * g2;
            float g3 = ag[3] + bg1; g3 = g3 > 0.f ? g3 : 0.01f * g3;
            __half2 o0 = __floats2half2_rn(tanhf(ay[0] + by0) * g0,
                                           tanhf(ay[1] + by1) * g1);
            __half2 o1 = __floats2half2_rn(tanhf(ay[2] + by0) * g2,
                                           tanhf(ay[3] + by1) * g3);
            *(__half2*)&g_Ehf[z][gm0    ][gn] = o0;
            *(__half2*)&g_Ehf[z][gm0 + 8][gn] = o1;
        }
    }
}

// ---------------------------------------------------------------------------
// score via HMMA: S = Eq @ (Eh.w)^T, N = Eq^2 @ (Eh^2)^T, split-K (KSL, B_).
// ---------------------------------------------------------------------------
#define SPITCH 136

__global__ __launch_bounds__(128)
void score_hmma_kernel(const float* __restrict__ W_att)
{
    __shared__ __align__(16) __half sq [32 * SPITCH];
    __shared__ __align__(16) __half shh[32 * SPITCH];
    __shared__ __align__(16) __half shw[32 * SPITCH];

    const int sl = blockIdx.x;
    const int b  = blockIdx.y;
    const int kb = sl * KCH;
    const int tid = threadIdx.x, lane = tid & 31, w = tid >> 5;

    #pragma unroll
    for (int i = 0; i < 4; i++){
        int idx = tid + i * 128;          // 0..511
        int r   = idx >> 4;               // 0..31
        int seg = idx & 15;               // 0..15
        uint4 vq = *(const uint4*)&g_Ehf[1][b*R_ + r][kb + seg*8];
        *(uint4*)&sq[r * SPITCH + seg*8] = vq;
        uint4 vh = *(const uint4*)&g_Ehf[0][b*R_ + r][kb + seg*8];
        *(uint4*)&shh[r * SPITCH + seg*8] = vh;
        const float* wp = W_att + kb + seg*8;
        float4 w0 = *(const float4*)wp;
        float4 w1 = *(const float4*)(wp + 4);
        const __half* h8 = (const __half*)&vh;
        __half o8[8];
        o8[0] = __float2half_rn(__half2float(h8[0]) * w0.x);
        o8[1] = __float2half_rn(__half2float(h8[1]) * w0.y);
        o8[2] = __float2half_rn(__half2float(h8[2]) * w0.z);
        o8[3] = __float2half_rn(__half2float(h8[3]) * w0.w);
        o8[4] = __float2half_rn(__half2float(h8[4]) * w1.x);
        o8[5] = __float2half_rn(__half2float(h8[5]) * w1.y);
        o8[6] = __float2half_rn(__half2float(h8[6]) * w1.z);
        o8[7] = __float2half_rn(__half2float(h8[7]) * w1.w);
        *(uint4*)&shw[r * SPITCH + seg*8] = *(uint4*)o8;
    }
    __syncthreads();

    const int wm = w & 1, wn = w >> 1;
    const int lr = lane & 15, lc = (lane >> 4) * 8;
    const uint32_t aB = smem_u32(sq);
    const uint32_t hB = smem_u32(shh);
    const uint32_t wB = smem_u32(shw);

    float cs[2][4] = {{0,0,0,0},{0,0,0,0}};
    float cn[2][4] = {{0,0,0,0},{0,0,0,0}};

    #pragma unroll
    for (int kk = 0; kk < KCH; kk += 16){
        uint32_t a[4], a2[4];
        LDSM_X4(a[0], a[1], a[2], a[3], aB + ((wm*16 + lr) * SPITCH + kk + lc) * 2);
        #pragma unroll
        for (int i = 0; i < 4; i++) a2[i] = sqr_h2(a[i]);

        uint32_t tw0, tw1, tw2, tw3;
        LDSM_X4(tw0, tw1, tw2, tw3, wB + ((wn*16 + lr) * SPITCH + kk + lc) * 2);
        uint32_t th0, th1, th2, th3;
        LDSM_X4(th0, th1, th2, th3, hB + ((wn*16 + lr) * SPITCH + kk + lc) * 2);

        uint32_t bS0[2] = {tw0, tw2}, bS1[2] = {tw1, tw3};
        uint32_t b20[2] = {sqr_h2(th0), sqr_h2(th2)};
        uint32_t b21[2] = {sqr_h2(th1), sqr_h2(th3)};

        MMA16816(cs[0], a, bS0);
        MMA16816(cs[1], a, bS1);
        MMA16816(cn[0], a2, b20);
        MMA16816(cn[1], a2, b21);
    }

    const int grp = lane >> 2, tig = lane & 3;
    const int q0 = wm * 16 + grp;
    #pragma unroll
    for (int t = 0; t < 2; t++){
        const int hc = wn * 16 + t * 8 + tig * 2;
        *(float2*)&g_spart[sl][b][q0    ][hc] = make_float2(cs[t][0], cs[t][1]);
        *(float2*)&g_spart[sl][b][q0 + 8][hc] = make_float2(cs[t][2], cs[t][3]);
        *(float2*)&g_npart[sl][b][q0    ][hc] = make_float2(cn[t][0], cn[t][1]);
        *(float2*)&g_npart[sl][b][q0 + 8][hc] = make_float2(cn[t][2], cn[t][3]);
    }
}

// ---------------------------------------------------------------------------
// feat (+ fused combine/softmax): block (dchunk, b), 256 thr.
// Phase 1: 8 warps x 4 q rows -> combine partials + masked softmax -> smem.
// Phase 2: feat = att @ hist, 2 d-columns per thread.
// ---------------------------------------------------------------------------
#define FEAT_SMEM ((1024 + 32 * 512) * 4)

__global__ __launch_bounds__(256)
void feat_kernel(const float* __restrict__ hist, const float* __restrict__ b_att_p,
                 float* __restrict__ out)
{
    extern __shared__ __align__(16) float fsm[];
    float* s_att  = fsm;              // [32][32]
    float* s_hist = fsm + 1024;       // [32][512]

    const int b   = blockIdx.y;
    const int d0  = blockIdx.x * 512;
    const int tid = threadIdx.x;
    const int lane = tid & 31, w = tid >> 5;

    // Phase 1: combine + masked softmax (warp w -> q rows w*4..w*4+3)
    #pragma unroll
    for (int j = 0; j < 4; j++){
        const int q = w * 4 + j;
        const int h = lane;
        float s = 0.f, n = 0.f;
        #pragma unroll
        for (int sl = 0; sl < KSL; sl++){
            s += g_spart[sl][b][q][h];
            n += g_npart[sl][b][q][h];
        }
        float x = s / fmaxf(sqrtf(n), 1e-12f) + b_att_p[0];
        bool valid = (h <= q);
        float xm = valid ? x : -1e30f;
        #pragma unroll
        for (int off = 16; off; off >>= 1)
            xm = fmaxf(xm, __shfl_xor_sync(0xffffffffu, xm, off));
        float e = valid ? expf(x - xm) : 0.f;
        float se = e;
        #pragma unroll
        for (int off = 16; off; off >>= 1)
            se += __shfl_xor_sync(0xffffffffu, se, off);
        s_att[q * 32 + h] = e / se;
    }

    // Phase 2 loads (independent of phase 1 in-flight)
    #pragma unroll
    for (int i = 0; i < 16; i++){
        int idx = tid + i * 256;
        int h   = idx >> 7;
        int c4  = (idx & 127) << 2;
        *(float4*)&s_hist[h * 512 + c4] =
            *(const float4*)(hist + (size_t)(b * R_ + h) * IN_ + d0 + c4);
    }
    __syncthreads();

    float acc0[32], acc1[32];
    #pragma unroll
    for (int q = 0; q < 32; q++){ acc0[q] = 0.f; acc1[q] = 0.f; }
    #pragma unroll
    for (int h = 0; h < 32; h++){
        float hv0 = s_hist[h * 512 + tid];
        float hv1 = s_hist[h * 512 + tid + 256];
        #pragma unroll
        for (int q = 0; q < 32; q++){
            float av = s_att[q * 32 + h];
            acc0[q] += av * hv0;
            acc1[q] += av * hv1;
        }
    }
    #pragma unroll
    for (int q = 0; q < 32; q++){
        out[(size_t)(b * R_ + q) * IN_ + d0 + tid]       = acc0[q];
        out[(size_t)(b * R_ + q) * IN_ + d0 + tid + 256] = acc1[q];
    }
}

// ---------------------------------------------------------------------------
extern "C" void kernel_launch(void* const* d_in, const int* in_sizes, int n_in,
                              void* d_out, int out_size)
{
    const float* hist = (const float*)d_in[0];
    const float* ques = (const float*)d_in[1];
    const float* Why  = (const float*)d_in[2];
    const float* bhy  = (const float*)d_in[3];
    const float* Whg  = (const float*)d_in[4];
    const float* bhg  = (const float*)d_in[5];
    const float* Wqy  = (const float*)d_in[6];
    const float* bqy  = (const float*)d_in[7];
    const float* Wqg  = (const float*)d_in[8];
    const float* bqg  = (const float*)d_in[9];
    const float* Watt = (const float*)d_in[10];
    const float* batt = (const float*)d_in[11];
    float* out = (float*)d_out;

    cudaFuncSetAttribute(embed_hmma_kernel,
                         cudaFuncAttributeMaxDynamicSharedMemorySize, EMB_SMEM);
    cudaFuncSetAttribute(feat_kernel,
                         cudaFuncAttributeMaxDynamicSharedMemorySize, FEAT_SMEM);

    conv_fused_kernel<<<6144, 256>>>(hist, ques, Why, Whg, Wqy, Wqg);
    embed_hmma_kernel<<<dim3(16, 32, 2), 256, EMB_SMEM>>>(bhy, bhg, bqy, bqg);
    score_hmma_kernel<<<dim3(KSL, B_), 128>>>(Watt);
    feat_kernel<<<dim3(IN_ / 512, B_), 256, FEAT_SMEM>>>(hist, batt, out);
}

// round 11
// speedup vs baseline: 1.0315x; 1.0315x over previous
#include <cuda_runtime.h>
#include <cuda_fp16.h>
#include <cstdint>
#include <math.h>

#define B_  64
#define R_  32
#define H_  1024
#define IN_ 2048
#define M_  (B_*R_)
#define KSL 8                 // score k-slices
#define KCH (H_/KSL)          // 128 k per slice

// ---------------- scratch (__device__ globals) -----------------------------
__device__ __align__(16) __half g_Ehf[2][M_][H_];          // embeds fp16
__device__ __align__(16) __half g_Xf[2][M_][IN_];          // A fp16 [M,K]
__device__ __align__(16) __half g_Wf[4][H_][IN_];          // B fp16 [N,K] (W^T)
__device__ __align__(16) float  g_spart[KSL][B_][R_][R_];  // partial scores
__device__ __align__(16) float  g_npart[KSL][B_][R_][R_];  // partial norms

// ---------------- helpers --------------------------------------------------
__device__ __forceinline__ uint32_t smem_u32(const void* p){
    uint32_t a;
    asm("{ .reg .u64 t; cvta.to.shared.u64 t, %1; cvt.u32.u64 %0, t; }" : "=r"(a) : "l"(p));
    return a;
}
__device__ __forceinline__ void cpasync16(uint32_t dst, const void* src){
    asm volatile("cp.async.cg.shared.global [%0], [%1], 16;" :: "r"(dst), "l"(src));
}
#define CP_COMMIT() asm volatile("cp.async.commit_group;" ::: "memory")

#define LDSM_X4(d0,d1,d2,d3,addr) \
    asm volatile("ldmatrix.sync.aligned.m8n8.x4.shared.b16 {%0,%1,%2,%3}, [%4];" \
        : "=r"(d0),"=r"(d1),"=r"(d2),"=r"(d3) : "r"(addr))

#define MMA16816(c, a, b) \
    asm volatile("mma.sync.aligned.m16n8k16.row.col.f32.f16.f16.f32 " \
        "{%0,%1,%2,%3}, {%4,%5,%6,%7}, {%8,%9}, {%0,%1,%2,%3};" \
        : "+f"((c)[0]),"+f"((c)[1]),"+f"((c)[2]),"+f"((c)[3]) \
        : "r"((a)[0]),"r"((a)[1]),"r"((a)[2]),"r"((a)[3]), "r"((b)[0]),"r"((b)[1]))

__device__ __forceinline__ uint32_t sqr_h2(uint32_t x){
    __half2 h = *reinterpret_cast<__half2*>(&x);
    __half2 r = __hmul2(h, h);
    return *reinterpret_cast<uint32_t*>(&r);
}

// ---------------------------------------------------------------------------
// fused conv: part 1 (X fp32->fp16), part 2 (W transpose fp32->fp16 [N,K])
// ---------------------------------------------------------------------------
__global__ __launch_bounds__(256)
void conv_fused_kernel(const float* __restrict__ hist, const float* __restrict__ ques,
                       const float* __restrict__ W0, const float* __restrict__ W1,
                       const float* __restrict__ W2, const float* __restrict__ W3)
{
    const int bx = blockIdx.x;
    const int tid = threadIdx.x;
    if (bx < 4096){
        const int z = bx >> 11;
        const int xb = bx & 2047;
        const float* X = z ? ques : hist;
        __half* dst = &g_Xf[z][0][0];
        size_t i = ((size_t)xb * 256 + tid) * 8;
        float4 v0 = *(const float4*)(X + i);
        float4 v1 = *(const float4*)(X + i + 4);
        __half2 h[4];
        h[0] = __floats2half2_rn(v0.x, v0.y);
        h[1] = __floats2half2_rn(v0.z, v0.w);
        h[2] = __floats2half2_rn(v1.x, v1.y);
        h[3] = __floats2half2_rn(v1.z, v1.w);
        *(uint4*)(dst + i) = *(uint4*)h;
    } else {
        const float* Ws[4] = {W0, W1, W2, W3};
        const int wb  = bx - 4096;
        const int br  = wb >> 9;
        const int rem = wb & 511;
        const int n0  = (rem >> 5) * 64;
        const int k0  = (rem & 31) * 64;
        const float* W = Ws[br];
        __shared__ float s[64][65];
        #pragma unroll
        for (int i = 0; i < 4; i++){
            int idx = tid + i * 256;
            int r = idx >> 4;
            int c = (idx & 15) * 4;
            float4 v = *(const float4*)(W + (size_t)(k0 + r) * H_ + n0 + c);
            s[r][c] = v.x; s[r][c+1] = v.y; s[r][c+2] = v.z; s[r][c+3] = v.w;
        }
        __syncthreads();
        int nl  = tid >> 2;
        int seg = (tid & 3) * 16;
        __half2 h[8];
        #pragma unroll
        for (int j = 0; j < 8; j++)
            h[j] = __floats2half2_rn(s[seg + 2*j][nl], s[seg + 2*j + 1][nl]);
        __half* o = &g_Wf[br][n0 + nl][k0 + seg];
        *(uint4*)(o)     = *(uint4*)&h[0];
        *(uint4*)(o + 8) = *(uint4*)&h[4];
    }
}

// ---------------------------------------------------------------------------
// embed GEMM: HMMA m16n8k16 fp16, dual-branch, 3-stage cp.async, BK=64.
// CTA: BM=128, BN=32/branch -> grid (16, 32, 2) = 1024 CTAs (tail ~1.5%).
// ---------------------------------------------------------------------------
#define PITCH  72
#define ST_A   (128 * PITCH * 2)
#define ST_Bb  (32 * PITCH * 2)
#define ST_TOT (ST_A + 2 * ST_Bb)
#define EMB_SMEM (3 * ST_TOT)

__global__ __launch_bounds__(256, 2)
void embed_hmma_kernel(const float* __restrict__ bhy, const float* __restrict__ bhg,
                       const float* __restrict__ bqy, const float* __restrict__ bqg)
{
    extern __shared__ __align__(16) char sm[];
    const uint32_t smu = smem_u32(sm);

    const int tid  = threadIdx.x;
    const int lane = tid & 31, wid = tid >> 5;
    const int wm = wid >> 1, wn = wid & 1;
    const int z  = blockIdx.z;
    const int m0 = blockIdx.x * 128;
    const int n0 = blockIdx.y * 32;

    const __half* Xf = &g_Xf[z][0][0];
    const __half* Wy = &g_Wf[2*z + 0][0][0];
    const __half* Wg = &g_Wf[2*z + 1][0][0];

    float acc[2][2][2][4];
    #pragma unroll
    for (int b = 0; b < 2; b++)
        #pragma unroll
        for (int mi = 0; mi < 2; mi++)
            #pragma unroll
            for (int ni = 0; ni < 2; ni++)
                #pragma unroll
                for (int r = 0; r < 4; r++) acc[b][mi][ni][r] = 0.f;

    auto load_stage = [&](int s){
        const int k0 = s * 64, buf = s % 3;
        const uint32_t base = smu + buf * ST_TOT;
        #pragma unroll
        for (int i = 0; i < 4; i++){
            int idx = tid + i * 256;
            int row = idx >> 3, seg = idx & 7;
            cpasync16(base + (row * PITCH + seg * 8) * 2,
                      Xf + (size_t)(m0 + row) * IN_ + k0 + seg * 8);
        }
        #pragma unroll
        for (int i = 0; i < 2; i++){
            int idx = tid + i * 256;
            int t = idx >> 8, r = (idx >> 3) & 31, seg = idx & 7;
            const __half* W = t ? Wg : Wy;
            cpasync16(base + ST_A + t * ST_Bb + (r * PITCH + seg * 8) * 2,
                      W + (size_t)(n0 + r) * IN_ + k0 + seg * 8);
        }
    };

    load_stage(0); CP_COMMIT();
    load_stage(1); CP_COMMIT();

    const int lr = lane & 15;
    const int lc = (lane >> 4) * 8;

    for (int s = 0; s < 32; s++){
        if (s + 2 < 32) load_stage(s + 2);
        CP_COMMIT();
        asm volatile("cp.async.wait_group 2;" ::: "memory");
        __syncthreads();

        const uint32_t base  = smu + (s % 3) * ST_TOT;
        const uint32_t bBase = base + ST_A;

        #pragma unroll
        for (int kk = 0; kk < 64; kk += 16){
            uint32_t a[2][4];
            #pragma unroll
            for (int mi = 0; mi < 2; mi++){
                uint32_t ad = base + ((wm*32 + mi*16 + lr) * PITCH + kk + lc) * 2;
                LDSM_X4(a[mi][0], a[mi][1], a[mi][2], a[mi][3], ad);
            }
            #pragma unroll
            for (int br = 0; br < 2; br++){
                uint32_t t0, t1, t2, t3;
                uint32_t bd = bBase + br * ST_Bb +
                              ((wn*16 + lr) * PITCH + kk + lc) * 2;
                LDSM_X4(t0, t1, t2, t3, bd);
                uint32_t b0[2] = {t0, t2};
                uint32_t b1[2] = {t1, t3};
                #pragma unroll
                for (int mi = 0; mi < 2; mi++){
                    MMA16816(acc[br][mi][0], a[mi], b0);
                    MMA16816(acc[br][mi][1], a[mi], b1);
                }
            }
        }
        __syncthreads();
    }

    const float* by = z ? bqy : bhy;
    const float* bg = z ? bqg : bhg;
    const int grp = lane >> 2, tig = lane & 3;
    #pragma unroll
    for (int mi = 0; mi < 2; mi++){
        #pragma unroll
        for (int ni = 0; ni < 2; ni++){
            const float* ay = acc[0][mi][ni];
            const float* ag = acc[1][mi][ni];
            const int gn  = n0 + wn*16 + ni*8 + tig*2;
            const int gm0 = m0 + wm*32 + mi*16 + grp;
            const float by0 = by[gn], by1 = by[gn+1];
            const float bg0 = bg[gn], bg1 = bg[gn+1];
            float g0 = ag[0] + bg0; g0 = g0 > 0.f ? g0 : 0.01f * g0;
            float g1 = ag[1] + bg1; g1 = g1 > 0.f ? g1 : 0.01f * g1;
            float g2 = ag[2] + bg0; g2 = g2 > 0.f ? g2 : 0.01f * g2;
            float g3 = ag[3] + bg1; g3 = g3 > 0.f ? g3 : 0.01f * g3;
            __half2 o0 = __floats2half2_rn(tanhf(ay[0] + by0) * g0,
                                           tanhf(ay[1] + by1) * g1);
            __half2 o1 = __floats2half2_rn(tanhf(ay[2] + by0) * g2,
                                           tanhf(ay[3] + by1) * g3);
            *(__half2*)&g_Ehf[z][gm0    ][gn] = o0;
            *(__half2*)&g_Ehf[z][gm0 + 8][gn] = o1;
        }
    }
}

// ---------------------------------------------------------------------------
// score via HMMA: S = Eq @ (Eh.w)^T, N = Eq^2 @ (Eh^2)^T, split-K (KSL, B_).
// ---------------------------------------------------------------------------
#define SPITCH 136

__global__ __launch_bounds__(128)
void score_hmma_kernel(const float* __restrict__ W_att)
{
    __shared__ __align__(16) __half sq [32 * SPITCH];
    __shared__ __align__(16) __half shh[32 * SPITCH];
    __shared__ __align__(16) __half shw[32 * SPITCH];

    const int sl = blockIdx.x;
    const int b  = blockIdx.y;
    const int kb = sl * KCH;
    const int tid = threadIdx.x, lane = tid & 31, w = tid >> 5;

    #pragma unroll
    for (int i = 0; i < 4; i++){
        int idx = tid + i * 128;
        int r   = idx >> 4;
        int seg = idx & 15;
        uint4 vq = *(const uint4*)&g_Ehf[1][b*R_ + r][kb + seg*8];
        *(uint4*)&sq[r * SPITCH + seg*8] = vq;
        uint4 vh = *(const uint4*)&g_Ehf[0][b*R_ + r][kb + seg*8];
        *(uint4*)&shh[r * SPITCH + seg*8] = vh;
        const float* wp = W_att + kb + seg*8;
        float4 w0 = *(const float4*)wp;
        float4 w1 = *(const float4*)(wp + 4);
        const __half* h8 = (const __half*)&vh;
        __half o8[8];
        o8[0] = __float2half_rn(__half2float(h8[0]) * w0.x);
        o8[1] = __float2half_rn(__half2float(h8[1]) * w0.y);
        o8[2] = __float2half_rn(__half2float(h8[2]) * w0.z);
        o8[3] = __float2half_rn(__half2float(h8[3]) * w0.w);
        o8[4] = __float2half_rn(__half2float(h8[4]) * w1.x);
        o8[5] = __float2half_rn(__half2float(h8[5]) * w1.y);
        o8[6] = __float2half_rn(__half2float(h8[6]) * w1.z);
        o8[7] = __float2half_rn(__half2float(h8[7]) * w1.w);
        *(uint4*)&shw[r * SPITCH + seg*8] = *(uint4*)o8;
    }
    __syncthreads();

    const int wm = w & 1, wn = w >> 1;
    const int lr = lane & 15, lc = (lane >> 4) * 8;
    const uint32_t aB = smem_u32(sq);
    const uint32_t hB = smem_u32(shh);
    const uint32_t wB = smem_u32(shw);

    float cs[2][4] = {{0,0,0,0},{0,0,0,0}};
    float cn[2][4] = {{0,0,0,0},{0,0,0,0}};

    #pragma unroll
    for (int kk = 0; kk < KCH; kk += 16){
        uint32_t a[4], a2[4];
        LDSM_X4(a[0], a[1], a[2], a[3], aB + ((wm*16 + lr) * SPITCH + kk + lc) * 2);
        #pragma unroll
        for (int i = 0; i < 4; i++) a2[i] = sqr_h2(a[i]);

        uint32_t tw0, tw1, tw2, tw3;
        LDSM_X4(tw0, tw1, tw2, tw3, wB + ((wn*16 + lr) * SPITCH + kk + lc) * 2);
        uint32_t th0, th1, th2, th3;
        LDSM_X4(th0, th1, th2, th3, hB + ((wn*16 + lr) * SPITCH + kk + lc) * 2);

        uint32_t bS0[2] = {tw0, tw2}, bS1[2] = {tw1, tw3};
        uint32_t b20[2] = {sqr_h2(th0), sqr_h2(th2)};
        uint32_t b21[2] = {sqr_h2(th1), sqr_h2(th3)};

        MMA16816(cs[0], a, bS0);
        MMA16816(cs[1], a, bS1);
        MMA16816(cn[0], a2, b20);
        MMA16816(cn[1], a2, b21);
    }

    const int grp = lane >> 2, tig = lane & 3;
    const int q0 = wm * 16 + grp;
    #pragma unroll
    for (int t = 0; t < 2; t++){
        const int hc = wn * 16 + t * 8 + tig * 2;
        *(float2*)&g_spart[sl][b][q0    ][hc] = make_float2(cs[t][0], cs[t][1]);
        *(float2*)&g_spart[sl][b][q0 + 8][hc] = make_float2(cs[t][2], cs[t][3]);
        *(float2*)&g_npart[sl][b][q0    ][hc] = make_float2(cn[t][0], cn[t][1]);
        *(float2*)&g_npart[sl][b][q0 + 8][hc] = make_float2(cn[t][2], cn[t][3]);
    }
}

// ---------------------------------------------------------------------------
// feat (+ fused combine/softmax): block (dchunk, b), 256 thr, <=128 regs.
// Phase 1: 8 warps x 4 q rows -> combine partials + masked softmax -> smem.
// Phase 2: feat = att @ hist; q-loop split in 2 halves (16 live acc pairs).
// ---------------------------------------------------------------------------
#define FEAT_SMEM ((1024 + 32 * 512) * 4)

__global__ __launch_bounds__(256, 2)
void feat_kernel(const float* __restrict__ hist, const float* __restrict__ b_att_p,
                 float* __restrict__ out)
{
    extern __shared__ __align__(16) float fsm[];
    float* s_att  = fsm;              // [32][32]
    float* s_hist = fsm + 1024;       // [32][512]

    const int b   = blockIdx.y;
    const int d0  = blockIdx.x * 512;
    const int tid = threadIdx.x;
    const int lane = tid & 31, w = tid >> 5;

    // Phase 1: combine + masked softmax (warp w -> q rows w*4..w*4+3)
    #pragma unroll
    for (int j = 0; j < 4; j++){
        const int q = w * 4 + j;
        const int h = lane;
        float s = 0.f, n = 0.f;
        #pragma unroll
        for (int sl = 0; sl < KSL; sl++){
            s += g_spart[sl][b][q][h];
            n += g_npart[sl][b][q][h];
        }
        float x = s / fmaxf(sqrtf(n), 1e-12f) + b_att_p[0];
        bool valid = (h <= q);
        float xm = valid ? x : -1e30f;
        #pragma unroll
        for (int off = 16; off; off >>= 1)
            xm = fmaxf(xm, __shfl_xor_sync(0xffffffffu, xm, off));
        float e = valid ? expf(x - xm) : 0.f;
        float se = e;
        #pragma unroll
        for (int off = 16; off; off >>= 1)
            se += __shfl_xor_sync(0xffffffffu, se, off);
        s_att[q * 32 + h] = e / se;
    }

    // Phase 2 loads
    #pragma unroll
    for (int i = 0; i < 16; i++){
        int idx = tid + i * 256;
        int h   = idx >> 7;
        int c4  = (idx & 127) << 2;
        *(float4*)&s_hist[h * 512 + c4] =
            *(const float4*)(hist + (size_t)(b * R_ + h) * IN_ + d0 + c4);
    }
    __syncthreads();

    // q-loop in two halves of 16 to cap live accumulators at 32 regs
    #pragma unroll
    for (int qh = 0; qh < 2; qh++){
        float acc0[16], acc1[16];
        #pragma unroll
        for (int q = 0; q < 16; q++){ acc0[q] = 0.f; acc1[q] = 0.f; }
        #pragma unroll
        for (int h = 0; h < 32; h++){
            float hv0 = s_hist[h * 512 + tid];
            float hv1 = s_hist[h * 512 + tid + 256];
            #pragma unroll
            for (int q = 0; q < 16; q++){
                float av = s_att[(qh * 16 + q) * 32 + h];
                acc0[q] += av * hv0;
                acc1[q] += av * hv1;
            }
        }
        #pragma unroll
        for (int q = 0; q < 16; q++){
            const int gq = b * R_ + qh * 16 + q;
            out[(size_t)gq * IN_ + d0 + tid]       = acc0[q];
            out[(size_t)gq * IN_ + d0 + tid + 256] = acc1[q];
        }
    }
}

// ---------------------------------------------------------------------------
extern "C" void kernel_launch(void* const* d_in, const int* in_sizes, int n_in,
                              void* d_out, int out_size)
{
    const float* hist = (const float*)d_in[0];
    const float* ques = (const float*)d_in[1];
    const float* Why  = (const float*)d_in[2];
    const float* bhy  = (const float*)d_in[3];
    const float* Whg  = (const float*)d_in[4];
    const float* bhg  = (const float*)d_in[5];
    const float* Wqy  = (const float*)d_in[6];
    const float* bqy  = (const float*)d_in[7];
    const float* Wqg  = (const float*)d_in[8];
    const float* bqg  = (const float*)d_in[9];
    const float* Watt = (const float*)d_in[10];
    const float* batt = (const float*)d_in[11];
    float* out = (float*)d_out;

    cudaFuncSetAttribute(embed_hmma_kernel,
                         cudaFuncAttributeMaxDynamicSharedMemorySize, EMB_SMEM);
    cudaFuncSetAttribute(feat_kernel,
                         cudaFuncAttributeMaxDynamicSharedMemorySize, FEAT_SMEM);

    conv_fused_kernel<<<6144, 256>>>(hist, ques, Why, Whg, Wqy, Wqg);
    embed_hmma_kernel<<<dim3(16, 32, 2), 256, EMB_SMEM>>>(bhy, bhg, bqy, bqg);
    score_hmma_kernel<<<dim3(KSL, B_), 128>>>(Watt);
    feat_kernel<<<dim3(IN_ / 512, B_), 256, FEAT_SMEM>>>(hist, batt, out);
}

// round 12
// speedup vs baseline: 1.0317x; 1.0002x over previous
#include <cuda_runtime.h>
#include <cuda_fp16.h>
#include <cstdint>
#include <math.h>

#define B_  64
#define R_  32
#define H_  1024
#define IN_ 2048
#define M_  (B_*R_)
#define KSL 8                 // score k-slices
#define KCH (H_/KSL)          // 128 k per slice

// ---------------- scratch (__device__ globals) -----------------------------
__device__ __align__(16) __half g_Ehf[2][M_][H_];          // embeds fp16
__device__ __align__(16) __half g_Xf[2][M_][IN_];          // A fp16 [M,K]
__device__ __align__(16) __half g_Wf[4][H_][IN_];          // B fp16 [N,K] (W^T)
__device__ __align__(16) float  g_spart[KSL][B_][R_][R_];  // partial scores
__device__ __align__(16) float  g_npart[KSL][B_][R_][R_];  // partial norms

// ---------------- helpers --------------------------------------------------
__device__ __forceinline__ uint32_t smem_u32(const void* p){
    uint32_t a;
    asm("{ .reg .u64 t; cvta.to.shared.u64 t, %1; cvt.u32.u64 %0, t; }" : "=r"(a) : "l"(p));
    return a;
}
__device__ __forceinline__ void cpasync16(uint32_t dst, const void* src){
    asm volatile("cp.async.cg.shared.global [%0], [%1], 16;" :: "r"(dst), "l"(src));
}
#define CP_COMMIT() asm volatile("cp.async.commit_group;" ::: "memory")

#define LDSM_X4(d0,d1,d2,d3,addr) \
    asm volatile("ldmatrix.sync.aligned.m8n8.x4.shared.b16 {%0,%1,%2,%3}, [%4];" \
        : "=r"(d0),"=r"(d1),"=r"(d2),"=r"(d3) : "r"(addr))

#define MMA16816(c, a, b) \
    asm volatile("mma.sync.aligned.m16n8k16.row.col.f32.f16.f16.f32 " \
        "{%0,%1,%2,%3}, {%4,%5,%6,%7}, {%8,%9}, {%0,%1,%2,%3};" \
        : "+f"((c)[0]),"+f"((c)[1]),"+f"((c)[2]),"+f"((c)[3]) \
        : "r"((a)[0]),"r"((a)[1]),"r"((a)[2]),"r"((a)[3]), "r"((b)[0]),"r"((b)[1]))

__device__ __forceinline__ uint32_t sqr_h2(uint32_t x){
    __half2 h = *reinterpret_cast<__half2*>(&x);
    __half2 r = __hmul2(h, h);
    return *reinterpret_cast<uint32_t*>(&r);
}

// ---------------------------------------------------------------------------
// fused conv: part 1 (X fp32->fp16), part 2 (W transpose fp32->fp16 [N,K])
// ---------------------------------------------------------------------------
__global__ __launch_bounds__(256)
void conv_fused_kernel(const float* __restrict__ hist, const float* __restrict__ ques,
                       const float* __restrict__ W0, const float* __restrict__ W1,
                       const float* __restrict__ W2, const float* __restrict__ W3)
{
    const int bx = blockIdx.x;
    const int tid = threadIdx.x;
    if (bx < 4096){
        const int z = bx >> 11;
        const int xb = bx & 2047;
        const float* X = z ? ques : hist;
        __half* dst = &g_Xf[z][0][0];
        size_t i = ((size_t)xb * 256 + tid) * 8;
        float4 v0 = *(const float4*)(X + i);
        float4 v1 = *(const float4*)(X + i + 4);
        __half2 h[4];
        h[0] = __floats2half2_rn(v0.x, v0.y);
        h[1] = __floats2half2_rn(v0.z, v0.w);
        h[2] = __floats2half2_rn(v1.x, v1.y);
        h[3] = __floats2half2_rn(v1.z, v1.w);
        *(uint4*)(dst + i) = *(uint4*)h;
    } else {
        const float* Ws[4] = {W0, W1, W2, W3};
        const int wb  = bx - 4096;
        const int br  = wb >> 9;
        const int rem = wb & 511;
        const int n0  = (rem >> 5) * 64;
        const int k0  = (rem & 31) * 64;
        const float* W = Ws[br];
        __shared__ float s[64][65];
        #pragma unroll
        for (int i = 0; i < 4; i++){
            int idx = tid + i * 256;
            int r = idx >> 4;
            int c = (idx & 15) * 4;
            float4 v = *(const float4*)(W + (size_t)(k0 + r) * H_ + n0 + c);
            s[r][c] = v.x; s[r][c+1] = v.y; s[r][c+2] = v.z; s[r][c+3] = v.w;
        }
        __syncthreads();
        int nl  = tid >> 2;
        int seg = (tid & 3) * 16;
        __half2 h[8];
        #pragma unroll
        for (int j = 0; j < 8; j++)
            h[j] = __floats2half2_rn(s[seg + 2*j][nl], s[seg + 2*j + 1][nl]);
        __half* o = &g_Wf[br][n0 + nl][k0 + seg];
        *(uint4*)(o)     = *(uint4*)&h[0];
        *(uint4*)(o + 8) = *(uint4*)&h[4];
    }
}

// ---------------------------------------------------------------------------
// embed GEMM: HMMA m16n8k16 fp16, dual-branch, 3-stage cp.async, BK=64.
// CTA: BM=128, BN=32/branch -> grid (16, 32, 2) = 1024 CTAs (tail ~1.5%).
// ---------------------------------------------------------------------------
#define PITCH  72
#define ST_A   (128 * PITCH * 2)
#define ST_Bb  (32 * PITCH * 2)
#define ST_TOT (ST_A + 2 * ST_Bb)
#define EMB_SMEM (3 * ST_TOT)

__global__ __launch_bounds__(256, 2)
void embed_hmma_kernel(const float* __restrict__ bhy, const float* __restrict__ bhg,
                       const float* __restrict__ bqy, const float* __restrict__ bqg)
{
    extern __shared__ __align__(16) char sm[];
    const uint32_t smu = smem_u32(sm);

    const int tid  = threadIdx.x;
    const int lane = tid & 31, wid = tid >> 5;
    const int wm = wid >> 1, wn = wid & 1;
    const int z  = blockIdx.z;
    const int m0 = blockIdx.x * 128;
    const int n0 = blockIdx.y * 32;

    const __half* Xf = &g_Xf[z][0][0];
    const __half* Wy = &g_Wf[2*z + 0][0][0];
    const __half* Wg = &g_Wf[2*z + 1][0][0];

    float acc[2][2][2][4];
    #pragma unroll
    for (int b = 0; b < 2; b++)
        #pragma unroll
        for (int mi = 0; mi < 2; mi++)
            #pragma unroll
            for (int ni = 0; ni < 2; ni++)
                #pragma unroll
                for (int r = 0; r < 4; r++) acc[b][mi][ni][r] = 0.f;

    auto load_stage = [&](int s){
        const int k0 = s * 64, buf = s % 3;
        const uint32_t base = smu + buf * ST_TOT;
        #pragma unroll
        for (int i = 0; i < 4; i++){
            int idx = tid + i * 256;
            int row = idx >> 3, seg = idx & 7;
            cpasync16(base + (row * PITCH + seg * 8) * 2,
                      Xf + (size_t)(m0 + row) * IN_ + k0 + seg * 8);
        }
        #pragma unroll
        for (int i = 0; i < 2; i++){
            int idx = tid + i * 256;
            int t = idx >> 8, r = (idx >> 3) & 31, seg = idx & 7;
            const __half* W = t ? Wg : Wy;
            cpasync16(base + ST_A + t * ST_Bb + (r * PITCH + seg * 8) * 2,
                      W + (size_t)(n0 + r) * IN_ + k0 + seg * 8);
        }
    };

    load_stage(0); CP_COMMIT();
    load_stage(1); CP_COMMIT();

    const int lr = lane & 15;
    const int lc = (lane >> 4) * 8;

    for (int s = 0; s < 32; s++){
        if (s + 2 < 32) load_stage(s + 2);
        CP_COMMIT();
        asm volatile("cp.async.wait_group 2;" ::: "memory");
        __syncthreads();

        const uint32_t base  = smu + (s % 3) * ST_TOT;
        const uint32_t bBase = base + ST_A;

        #pragma unroll
        for (int kk = 0; kk < 64; kk += 16){
            uint32_t a[2][4];
            #pragma unroll
            for (int mi = 0; mi < 2; mi++){
                uint32_t ad = base + ((wm*32 + mi*16 + lr) * PITCH + kk + lc) * 2;
                LDSM_X4(a[mi][0], a[mi][1], a[mi][2], a[mi][3], ad);
            }
            #pragma unroll
            for (int br = 0; br < 2; br++){
                uint32_t t0, t1, t2, t3;
                uint32_t bd = bBase + br * ST_Bb +
                              ((wn*16 + lr) * PITCH + kk + lc) * 2;
                LDSM_X4(t0, t1, t2, t3, bd);
                uint32_t b0[2] = {t0, t2};
                uint32_t b1[2] = {t1, t3};
                #pragma unroll
                for (int mi = 0; mi < 2; mi++){
                    MMA16816(acc[br][mi][0], a[mi], b0);
                    MMA16816(acc[br][mi][1], a[mi], b1);
                }
            }
        }
        __syncthreads();
    }

    const float* by = z ? bqy : bhy;
    const float* bg = z ? bqg : bhg;
    const int grp = lane >> 2, tig = lane & 3;
    #pragma unroll
    for (int mi = 0; mi < 2; mi++){
        #pragma unroll
        for (int ni = 0; ni < 2; ni++){
            const float* ay = acc[0][mi][ni];
            const float* ag = acc[1][mi][ni];
            const int gn  = n0 + wn*16 + ni*8 + tig*2;
            const int gm0 = m0 + wm*32 + mi*16 + grp;
            const float by0 = by[gn], by1 = by[gn+1];
            const float bg0 = bg[gn], bg1 = bg[gn+1];
            float g0 = ag[0] + bg0; g0 = g0 > 0.f ? g0 : 0.01f * g0;
            float g1 = ag[1] + bg1; g1 = g1 > 0.f ? g1 : 0.01f * g1;
            float g2 = ag[2] + bg0; g2 = g2 > 0.f ? g2 : 0.01f * g2;
            float g3 = ag[3] + bg1; g3 = g3 > 0.f ? g3 : 0.01f * g3;
            __half2 o0 = __floats2half2_rn(tanhf(ay[0] + by0) * g0,
                                           tanhf(ay[1] + by1) * g1);
            __half2 o1 = __floats2half2_rn(tanhf(ay[2] + by0) * g2,
                                           tanhf(ay[3] + by1) * g3);
            *(__half2*)&g_Ehf[z][gm0    ][gn] = o0;
            *(__half2*)&g_Ehf[z][gm0 + 8][gn] = o1;
        }
    }
}

// ---------------------------------------------------------------------------
// score via HMMA: S = Eq @ (Eh.w)^T, N = Eq^2 @ (Eh^2)^T, split-K (KSL, B_).
// ---------------------------------------------------------------------------
#define SPITCH 136

__global__ __launch_bounds__(128)
void score_hmma_kernel(const float* __restrict__ W_att)
{
    __shared__ __align__(16) __half sq [32 * SPITCH];
    __shared__ __align__(16) __half shh[32 * SPITCH];
    __shared__ __align__(16) __half shw[32 * SPITCH];

    const int sl = blockIdx.x;
    const int b  = blockIdx.y;
    const int kb = sl * KCH;
    const int tid = threadIdx.x, lane = tid & 31, w = tid >> 5;

    #pragma unroll
    for (int i = 0; i < 4; i++){
        int idx = tid + i * 128;
        int r   = idx >> 4;
        int seg = idx & 15;
        uint4 vq = *(const uint4*)&g_Ehf[1][b*R_ + r][kb + seg*8];
        *(uint4*)&sq[r * SPITCH + seg*8] = vq;
        uint4 vh = *(const uint4*)&g_Ehf[0][b*R_ + r][kb + seg*8];
        *(uint4*)&shh[r * SPITCH + seg*8] = vh;
        const float* wp = W_att + kb + seg*8;
        float4 w0 = *(const float4*)wp;
        float4 w1 = *(const float4*)(wp + 4);
        const __half* h8 = (const __half*)&vh;
        __half o8[8];
        o8[0] = __float2half_rn(__half2float(h8[0]) * w0.x);
        o8[1] = __float2half_rn(__half2float(h8[1]) * w0.y);
        o8[2] = __float2half_rn(__half2float(h8[2]) * w0.z);
        o8[3] = __float2half_rn(__half2float(h8[3]) * w0.w);
        o8[4] = __float2half_rn(__half2float(h8[4]) * w1.x);
        o8[5] = __float2half_rn(__half2float(h8[5]) * w1.y);
        o8[6] = __float2half_rn(__half2float(h8[6]) * w1.z);
        o8[7] = __float2half_rn(__half2float(h8[7]) * w1.w);
        *(uint4*)&shw[r * SPITCH + seg*8] = *(uint4*)o8;
    }
    __syncthreads();

    const int wm = w & 1, wn = w >> 1;
    const int lr = lane & 15, lc = (lane >> 4) * 8;
    const uint32_t aB = smem_u32(sq);
    const uint32_t hB = smem_u32(shh);
    const uint32_t wB = smem_u32(shw);

    float cs[2][4] = {{0,0,0,0},{0,0,0,0}};
    float cn[2][4] = {{0,0,0,0},{0,0,0,0}};

    #pragma unroll
    for (int kk = 0; kk < KCH; kk += 16){
        uint32_t a[4], a2[4];
        LDSM_X4(a[0], a[1], a[2], a[3], aB + ((wm*16 + lr) * SPITCH + kk + lc) * 2);
        #pragma unroll
        for (int i = 0; i < 4; i++) a2[i] = sqr_h2(a[i]);

        uint32_t tw0, tw1, tw2, tw3;
        LDSM_X4(tw0, tw1, tw2, tw3, wB + ((wn*16 + lr) * SPITCH + kk + lc) * 2);
        uint32_t th0, th1, th2, th3;
        LDSM_X4(th0, th1, th2, th3, hB + ((wn*16 + lr) * SPITCH + kk + lc) * 2);

        uint32_t bS0[2] = {tw0, tw2}, bS1[2] = {tw1, tw3};
        uint32_t b20[2] = {sqr_h2(th0), sqr_h2(th2)};
        uint32_t b21[2] = {sqr_h2(th1), sqr_h2(th3)};

        MMA16816(cs[0], a, bS0);
        MMA16816(cs[1], a, bS1);
        MMA16816(cn[0], a2, b20);
        MMA16816(cn[1], a2, b21);
    }

    const int grp = lane >> 2, tig = lane & 3;
    const int q0 = wm * 16 + grp;
    #pragma unroll
    for (int t = 0; t < 2; t++){
        const int hc = wn * 16 + t * 8 + tig * 2;
        *(float2*)&g_spart[sl][b][q0    ][hc] = make_float2(cs[t][0], cs[t][1]);
        *(float2*)&g_spart[sl][b][q0 + 8][hc] = make_float2(cs[t][2], cs[t][3]);
        *(float2*)&g_npart[sl][b][q0    ][hc] = make_float2(cn[t][0], cn[t][1]);
        *(float2*)&g_npart[sl][b][q0 + 8][hc] = make_float2(cn[t][2], cn[t][3]);
    }
}

// ---------------------------------------------------------------------------
// feat (+ fused combine/softmax): block (dchunk, b), 256 thr.
// Phase 1: 8 warps x 4 q rows -> combine partials + masked softmax -> smem (4KB).
// Phase 2: hist column values in REGISTERS (no hist smem), q processed
// serially with immediate store. ~105 live regs, no spills.
// ---------------------------------------------------------------------------
#define FEAT_SMEM (1024 * 4)

__global__ __launch_bounds__(256, 2)
void feat_kernel(const float* __restrict__ hist, const float* __restrict__ b_att_p,
                 float* __restrict__ out)
{
    extern __shared__ __align__(16) float fsm[];
    float* s_att = fsm;               // [32][32]

    const int b   = blockIdx.y;
    const int d0  = blockIdx.x * 512;
    const int tid = threadIdx.x;
    const int lane = tid & 31, w = tid >> 5;

    // Phase 1: combine + masked softmax (warp w -> q rows w*4..w*4+3)
    #pragma unroll
    for (int j = 0; j < 4; j++){
        const int q = w * 4 + j;
        const int h = lane;
        float s = 0.f, n = 0.f;
        #pragma unroll
        for (int sl = 0; sl < KSL; sl++){
            s += g_spart[sl][b][q][h];
            n += g_npart[sl][b][q][h];
        }
        float x = s / fmaxf(sqrtf(n), 1e-12f) + b_att_p[0];
        bool valid = (h <= q);
        float xm = valid ? x : -1e30f;
        #pragma unroll
        for (int off = 16; off; off >>= 1)
            xm = fmaxf(xm, __shfl_xor_sync(0xffffffffu, xm, off));
        float e = valid ? expf(x - xm) : 0.f;
        float se = e;
        #pragma unroll
        for (int off = 16; off; off >>= 1)
            se += __shfl_xor_sync(0xffffffffu, se, off);
        s_att[q * 32 + h] = e / se;
    }

    // Phase 2: hist columns into registers (coalesced LDG, high MLP)
    const float* hb = hist + (size_t)(b * R_) * IN_ + d0 + tid;
    float hv0[32], hv1[32];
    #pragma unroll
    for (int h = 0; h < 32; h++){
        hv0[h] = hb[(size_t)h * IN_];
        hv1[h] = hb[(size_t)h * IN_ + 256];
    }
    __syncthreads();

    float* ob = out + (size_t)(b * R_) * IN_ + d0 + tid;
    #pragma unroll 1
    for (int q = 0; q < 32; q++){
        float4 at[8];
        #pragma unroll
        for (int j = 0; j < 8; j++)
            at[j] = *(float4*)&s_att[q * 32 + j * 4];
        float a0 = 0.f, a1 = 0.f;
        #pragma unroll
        for (int j = 0; j < 8; j++){
            const float* av = &at[j].x;
            #pragma unroll
            for (int k = 0; k < 4; k++){
                a0 += av[k] * hv0[j * 4 + k];
                a1 += av[k] * hv1[j * 4 + k];
            }
        }
        ob[(size_t)q * IN_]       = a0;
        ob[(size_t)q * IN_ + 256] = a1;
    }
}

// ---------------------------------------------------------------------------
extern "C" void kernel_launch(void* const* d_in, const int* in_sizes, int n_in,
                              void* d_out, int out_size)
{
    const float* hist = (const float*)d_in[0];
    const float* ques = (const float*)d_in[1];
    const float* Why  = (const float*)d_in[2];
    const float* bhy  = (const float*)d_in[3];
    const float* Whg  = (const float*)d_in[4];
    const float* bhg  = (const float*)d_in[5];
    const float* Wqy  = (const float*)d_in[6];
    const float* bqy  = (const float*)d_in[7];
    const float* Wqg  = (const float*)d_in[8];
    const float* bqg  = (const float*)d_in[9];
    const float* Watt = (const float*)d_in[10];
    const float* batt = (const float*)d_in[11];
    float* out = (float*)d_out;

    cudaFuncSetAttribute(embed_hmma_kernel,
                         cudaFuncAttributeMaxDynamicSharedMemorySize, EMB_SMEM);
    cudaFuncSetAttribute(feat_kernel,
                         cudaFuncAttributeMaxDynamicSharedMemorySize, FEAT_SMEM);

    conv_fused_kernel<<<6144, 256>>>(hist, ques, Why, Whg, Wqy, Wqg);
    embed_hmma_kernel<<<dim3(16, 32, 2), 256, EMB_SMEM>>>(bhy, bhg, bqy, bqg);
    score_hmma_kernel<<<dim3(KSL, B_), 128>>>(Watt);
    feat_kernel<<<dim3(IN_ / 512, B_), 256, FEAT_SMEM>>>(hist, batt, out);
}

// round 13
// speedup vs baseline: 1.0352x; 1.0034x over previous
#include <cuda_runtime.h>
#include <cuda_fp16.h>
#include <cstdint>
#include <math.h>

#define B_  64
#define R_  32
#define H_  1024
#define IN_ 2048
#define M_  (B_*R_)
#define KSL 8                 // score k-slices
#define KCH (H_/KSL)          // 128 k per slice

// ---------------- scratch (__device__ globals) -----------------------------
__device__ __align__(16) __half g_Ehf[2][M_][H_];          // embeds fp16
__device__ __align__(16) __half g_Xf[2][M_][IN_];          // A fp16 [M,K]
__device__ __align__(16) __half g_Wf[4][H_][IN_];          // B fp16 [N,K] (W^T)
__device__ __align__(16) float  g_spart[KSL][B_][R_][R_];  // partial scores
__device__ __align__(16) float  g_npart[KSL][B_][R_][R_];  // partial norms

// ---------------- helpers --------------------------------------------------
__device__ __forceinline__ uint32_t smem_u32(const void* p){
    uint32_t a;
    asm("{ .reg .u64 t; cvta.to.shared.u64 t, %1; cvt.u32.u64 %0, t; }" : "=r"(a) : "l"(p));
    return a;
}
__device__ __forceinline__ void cpasync16(uint32_t dst, const void* src){
    asm volatile("cp.async.cg.shared.global [%0], [%1], 16;" :: "r"(dst), "l"(src));
}
#define CP_COMMIT() asm volatile("cp.async.commit_group;" ::: "memory")

#define LDSM_X4(d0,d1,d2,d3,addr) \
    asm volatile("ldmatrix.sync.aligned.m8n8.x4.shared.b16 {%0,%1,%2,%3}, [%4];" \
        : "=r"(d0),"=r"(d1),"=r"(d2),"=r"(d3) : "r"(addr))

#define MMA16816(c, a, b) \
    asm volatile("mma.sync.aligned.m16n8k16.row.col.f32.f16.f16.f32 " \
        "{%0,%1,%2,%3}, {%4,%5,%6,%7}, {%8,%9}, {%0,%1,%2,%3};" \
        : "+f"((c)[0]),"+f"((c)[1]),"+f"((c)[2]),"+f"((c)[3]) \
        : "r"((a)[0]),"r"((a)[1]),"r"((a)[2]),"r"((a)[3]), "r"((b)[0]),"r"((b)[1]))

__device__ __forceinline__ uint32_t sqr_h2(uint32_t x){
    __half2 h = *reinterpret_cast<__half2*>(&x);
    __half2 r = __hmul2(h, h);
    return *reinterpret_cast<uint32_t*>(&r);
}

// ---------------------------------------------------------------------------
// fused conv: part 1 (X fp32->fp16), part 2 (W transpose fp32->fp16 [N,K])
// ---------------------------------------------------------------------------
__global__ __launch_bounds__(256)
void conv_fused_kernel(const float* __restrict__ hist, const float* __restrict__ ques,
                       const float* __restrict__ W0, const float* __restrict__ W1,
                       const float* __restrict__ W2, const float* __restrict__ W3)
{
    const int bx = blockIdx.x;
    const int tid = threadIdx.x;
    if (bx < 4096){
        const int z = bx >> 11;
        const int xb = bx & 2047;
        const float* X = z ? ques : hist;
        __half* dst = &g_Xf[z][0][0];
        size_t i = ((size_t)xb * 256 + tid) * 8;
        float4 v0 = *(const float4*)(X + i);
        float4 v1 = *(const float4*)(X + i + 4);
        __half2 h[4];
        h[0] = __floats2half2_rn(v0.x, v0.y);
        h[1] = __floats2half2_rn(v0.z, v0.w);
        h[2] = __floats2half2_rn(v1.x, v1.y);
        h[3] = __floats2half2_rn(v1.z, v1.w);
        *(uint4*)(dst + i) = *(uint4*)h;
    } else {
        const float* Ws[4] = {W0, W1, W2, W3};
        const int wb  = bx - 4096;
        const int br  = wb >> 9;
        const int rem = wb & 511;
        const int n0  = (rem >> 5) * 64;
        const int k0  = (rem & 31) * 64;
        const float* W = Ws[br];
        __shared__ float s[64][65];
        #pragma unroll
        for (int i = 0; i < 4; i++){
            int idx = tid + i * 256;
            int r = idx >> 4;
            int c = (idx & 15) * 4;
            float4 v = *(const float4*)(W + (size_t)(k0 + r) * H_ + n0 + c);
            s[r][c] = v.x; s[r][c+1] = v.y; s[r][c+2] = v.z; s[r][c+3] = v.w;
        }
        __syncthreads();
        int nl  = tid >> 2;
        int seg = (tid & 3) * 16;
        __half2 h[8];
        #pragma unroll
        for (int j = 0; j < 8; j++)
            h[j] = __floats2half2_rn(s[seg + 2*j][nl], s[seg + 2*j + 1][nl]);
        __half* o = &g_Wf[br][n0 + nl][k0 + seg];
        *(uint4*)(o)     = *(uint4*)&h[0];
        *(uint4*)(o + 8) = *(uint4*)&h[4];
    }
}

// ---------------------------------------------------------------------------
// embed GEMM: HMMA m16n8k16 fp16, dual-branch, 3-stage cp.async, BK=64.
// ONE __syncthreads per K-iter: loads for stage s+2 are issued AFTER the
// barrier that retires all reads of buffer (s+2)%3 (== (s-1)%3).
// CTA: BM=128, BN=32/branch -> grid (16, 32, 2) = 1024 CTAs.
// ---------------------------------------------------------------------------
#define PITCH  72
#define ST_A   (128 * PITCH * 2)
#define ST_Bb  (32 * PITCH * 2)
#define ST_TOT (ST_A + 2 * ST_Bb)
#define EMB_SMEM (3 * ST_TOT)

__global__ __launch_bounds__(256, 2)
void embed_hmma_kernel(const float* __restrict__ bhy, const float* __restrict__ bhg,
                       const float* __restrict__ bqy, const float* __restrict__ bqg)
{
    extern __shared__ __align__(16) char sm[];
    const uint32_t smu = smem_u32(sm);

    const int tid  = threadIdx.x;
    const int lane = tid & 31, wid = tid >> 5;
    const int wm = wid >> 1, wn = wid & 1;
    const int z  = blockIdx.z;
    const int m0 = blockIdx.x * 128;
    const int n0 = blockIdx.y * 32;

    const __half* Xf = &g_Xf[z][0][0];
    const __half* Wy = &g_Wf[2*z + 0][0][0];
    const __half* Wg = &g_Wf[2*z + 1][0][0];

    float acc[2][2][2][4];
    #pragma unroll
    for (int b = 0; b < 2; b++)
        #pragma unroll
        for (int mi = 0; mi < 2; mi++)
            #pragma unroll
            for (int ni = 0; ni < 2; ni++)
                #pragma unroll
                for (int r = 0; r < 4; r++) acc[b][mi][ni][r] = 0.f;

    auto load_stage = [&](int s){
        const int k0 = s * 64, buf = s % 3;
        const uint32_t base = smu + buf * ST_TOT;
        #pragma unroll
        for (int i = 0; i < 4; i++){
            int idx = tid + i * 256;
            int row = idx >> 3, seg = idx & 7;
            cpasync16(base + (row * PITCH + seg * 8) * 2,
                      Xf + (size_t)(m0 + row) * IN_ + k0 + seg * 8);
        }
        #pragma unroll
        for (int i = 0; i < 2; i++){
            int idx = tid + i * 256;
            int t = idx >> 8, r = (idx >> 3) & 31, seg = idx & 7;
            const __half* W = t ? Wg : Wy;
            cpasync16(base + ST_A + t * ST_Bb + (r * PITCH + seg * 8) * 2,
                      W + (size_t)(n0 + r) * IN_ + k0 + seg * 8);
        }
    };

    load_stage(0); CP_COMMIT();
    load_stage(1); CP_COMMIT();

    const int lr = lane & 15;
    const int lc = (lane >> 4) * 8;

    for (int s = 0; s < 32; s++){
        // stage s resident: newest committed group is s+1 -> wait_group 1.
        if (s < 31) asm volatile("cp.async.wait_group 1;" ::: "memory");
        else        asm volatile("cp.async.wait_group 0;" ::: "memory");
        __syncthreads();
        if (s + 2 < 32){ load_stage(s + 2); CP_COMMIT(); }

        const uint32_t base  = smu + (s % 3) * ST_TOT;
        const uint32_t bBase = base + ST_A;

        #pragma unroll
        for (int kk = 0; kk < 64; kk += 16){
            uint32_t a[2][4];
            #pragma unroll
            for (int mi = 0; mi < 2; mi++){
                uint32_t ad = base + ((wm*32 + mi*16 + lr) * PITCH + kk + lc) * 2;
                LDSM_X4(a[mi][0], a[mi][1], a[mi][2], a[mi][3], ad);
            }
            #pragma unroll
            for (int br = 0; br < 2; br++){
                uint32_t t0, t1, t2, t3;
                uint32_t bd = bBase + br * ST_Bb +
                              ((wn*16 + lr) * PITCH + kk + lc) * 2;
                LDSM_X4(t0, t1, t2, t3, bd);
                uint32_t b0[2] = {t0, t2};
                uint32_t b1[2] = {t1, t3};
                #pragma unroll
                for (int mi = 0; mi < 2; mi++){
                    MMA16816(acc[br][mi][0], a[mi], b0);
                    MMA16816(acc[br][mi][1], a[mi], b1);
                }
            }
        }
    }

    const float* by = z ? bqy : bhy;
    const float* bg = z ? bqg : bhg;
    const int grp = lane >> 2, tig = lane & 3;
    #pragma unroll
    for (int mi = 0; mi < 2; mi++){
        #pragma unroll
        for (int ni = 0; ni < 2; ni++){
            const float* ay = acc[0][mi][ni];
            const float* ag = acc[1][mi][ni];
            const int gn  = n0 + wn*16 + ni*8 + tig*2;
            const int gm0 = m0 + wm*32 + mi*16 + grp;
            const float by0 = by[gn], by1 = by[gn+1];
            const float bg0 = bg[gn], bg1 = bg[gn+1];
            float g0 = ag[0] + bg0; g0 = g0 > 0.f ? g0 : 0.01f * g0;
            float g1 = ag[1] + bg1; g1 = g1 > 0.f ? g1 : 0.01f * g1;
            float g2 = ag[2] + bg0; g2 = g2 > 0.f ? g2 : 0.01f * g2;
            float g3 = ag[3] + bg1; g3 = g3 > 0.f ? g3 : 0.01f * g3;
            __half2 o0 = __floats2half2_rn(tanhf(ay[0] + by0) * g0,
                                           tanhf(ay[1] + by1) * g1);
            __half2 o1 = __floats2half2_rn(tanhf(ay[2] + by0) * g2,
                                           tanhf(ay[3] + by1) * g3);
            *(__half2*)&g_Ehf[z][gm0    ][gn] = o0;
            *(__half2*)&g_Ehf[z][gm0 + 8][gn] = o1;
        }
    }
}

// ---------------------------------------------------------------------------
// score via HMMA: S = Eq @ (Eh.w)^T, N = Eq^2 @ (Eh^2)^T, split-K (KSL, B_).
// ---------------------------------------------------------------------------
#define SPITCH 136

__global__ __launch_bounds__(128)
void score_hmma_kernel(const float* __restrict__ W_att)
{
    __shared__ __align__(16) __half sq [32 * SPITCH];
    __shared__ __align__(16) __half shh[32 * SPITCH];
    __shared__ __align__(16) __half shw[32 * SPITCH];

    const int sl = blockIdx.x;
    const int b  = blockIdx.y;
    const int kb = sl * KCH;
    const int tid = threadIdx.x, lane = tid & 31, w = tid >> 5;

    #pragma unroll
    for (int i = 0; i < 4; i++){
        int idx = tid + i * 128;
        int r   = idx >> 4;
        int seg = idx & 15;
        uint4 vq = *(const uint4*)&g_Ehf[1][b*R_ + r][kb + seg*8];
        *(uint4*)&sq[r * SPITCH + seg*8] = vq;
        uint4 vh = *(const uint4*)&g_Ehf[0][b*R_ + r][kb + seg*8];
        *(uint4*)&shh[r * SPITCH + seg*8] = vh;
        const float* wp = W_att + kb + seg*8;
        float4 w0 = *(const float4*)wp;
        float4 w1 = *(const float4*)(wp + 4);
        const __half* h8 = (const __half*)&vh;
        __half o8[8];
        o8[0] = __float2half_rn(__half2float(h8[0]) * w0.x);
        o8[1] = __float2half_rn(__half2float(h8[1]) * w0.y);
        o8[2] = __float2half_rn(__half2float(h8[2]) * w0.z);
        o8[3] = __float2half_rn(__half2float(h8[3]) * w0.w);
        o8[4] = __float2half_rn(__half2float(h8[4]) * w1.x);
        o8[5] = __float2half_rn(__half2float(h8[5]) * w1.y);
        o8[6] = __float2half_rn(__half2float(h8[6]) * w1.z);
        o8[7] = __float2half_rn(__half2float(h8[7]) * w1.w);
        *(uint4*)&shw[r * SPITCH + seg*8] = *(uint4*)o8;
    }
    __syncthreads();

    const int wm = w & 1, wn = w >> 1;
    const int lr = lane & 15, lc = (lane >> 4) * 8;
    const uint32_t aB = smem_u32(sq);
    const uint32_t hB = smem_u32(shh);
    const uint32_t wB = smem_u32(shw);

    float cs[2][4] = {{0,0,0,0},{0,0,0,0}};
    float cn[2][4] = {{0,0,0,0},{0,0,0,0}};

    #pragma unroll
    for (int kk = 0; kk < KCH; kk += 16){
        uint32_t a[4], a2[4];
        LDSM_X4(a[0], a[1], a[2], a[3], aB + ((wm*16 + lr) * SPITCH + kk + lc) * 2);
        #pragma unroll
        for (int i = 0; i < 4; i++) a2[i] = sqr_h2(a[i]);

        uint32_t tw0, tw1, tw2, tw3;
        LDSM_X4(tw0, tw1, tw2, tw3, wB + ((wn*16 + lr) * SPITCH + kk + lc) * 2);
        uint32_t th0, th1, th2, th3;
        LDSM_X4(th0, th1, th2, th3, hB + ((wn*16 + lr) * SPITCH + kk + lc) * 2);

        uint32_t bS0[2] = {tw0, tw2}, bS1[2] = {tw1, tw3};
        uint32_t b20[2] = {sqr_h2(th0), sqr_h2(th2)};
        uint32_t b21[2] = {sqr_h2(th1), sqr_h2(th3)};

        MMA16816(cs[0], a, bS0);
        MMA16816(cs[1], a, bS1);
        MMA16816(cn[0], a2, b20);
        MMA16816(cn[1], a2, b21);
    }

    const int grp = lane >> 2, tig = lane & 3;
    const int q0 = wm * 16 + grp;
    #pragma unroll
    for (int t = 0; t < 2; t++){
        const int hc = wn * 16 + t * 8 + tig * 2;
        *(float2*)&g_spart[sl][b][q0    ][hc] = make_float2(cs[t][0], cs[t][1]);
        *(float2*)&g_spart[sl][b][q0 + 8][hc] = make_float2(cs[t][2], cs[t][3]);
        *(float2*)&g_npart[sl][b][q0    ][hc] = make_float2(cn[t][0], cn[t][1]);
        *(float2*)&g_npart[sl][b][q0 + 8][hc] = make_float2(cn[t][2], cn[t][3]);
    }
}

// ---------------------------------------------------------------------------
// feat (+ fused combine/softmax): grid (IN_/256, B_) = 512 blocks, 256 thr.
// Phase 1: combine partials + masked softmax -> smem (4KB).
// Phase 2: 1 d-column per thread, hist column in registers, q serial.
// ---------------------------------------------------------------------------
#define FEAT_SMEM (1024 * 4)

__global__ __launch_bounds__(256)
void feat_kernel(const float* __restrict__ hist, const float* __restrict__ b_att_p,
                 float* __restrict__ out)
{
    extern __shared__ __align__(16) float fsm[];
    float* s_att = fsm;               // [32][32]

    const int b   = blockIdx.y;
    const int d0  = blockIdx.x * 256;
    const int tid = threadIdx.x;
    const int lane = tid & 31, w = tid >> 5;

    // Phase 1: combine + masked softmax (warp w -> q rows w*4..w*4+3)
    #pragma unroll
    for (int j = 0; j < 4; j++){
        const int q = w * 4 + j;
        const int h = lane;
        float s = 0.f, n = 0.f;
        #pragma unroll
        for (int sl = 0; sl < KSL; sl++){
            s += g_spart[sl][b][q][h];
            n += g_npart[sl][b][q][h];
        }
        float x = s / fmaxf(sqrtf(n), 1e-12f) + b_att_p[0];
        bool valid = (h <= q);
        float xm = valid ? x : -1e30f;
        #pragma unroll
        for (int off = 16; off; off >>= 1)
            xm = fmaxf(xm, __shfl_xor_sync(0xffffffffu, xm, off));
        float e = valid ? expf(x - xm) : 0.f;
        float se = e;
        #pragma unroll
        for (int off = 16; off; off >>= 1)
            se += __shfl_xor_sync(0xffffffffu, se, off);
        s_att[q * 32 + h] = e / se;
    }

    // Phase 2: this thread's hist column into registers (coalesced, MLP 32)
    const float* hb = hist + (size_t)(b * R_) * IN_ + d0 + tid;
    float hv[32];
    #pragma unroll
    for (int h = 0; h < 32; h++)
        hv[h] = hb[(size_t)h * IN_];
    __syncthreads();

    float* ob = out + (size_t)(b * R_) * IN_ + d0 + tid;
    #pragma unroll 1
    for (int q = 0; q < 32; q++){
        float4 at[8];
        #pragma unroll
        for (int j = 0; j < 8; j++)
            at[j] = *(float4*)&s_att[q * 32 + j * 4];
        float a0 = 0.f;
        #pragma unroll
        for (int j = 0; j < 8; j++){
            const float* av = &at[j].x;
            #pragma unroll
            for (int k = 0; k < 4; k++)
                a0 += av[k] * hv[j * 4 + k];
        }
        ob[(size_t)q * IN_] = a0;
    }
}

// ---------------------------------------------------------------------------
extern "C" void kernel_launch(void* const* d_in, const int* in_sizes, int n_in,
                              void* d_out, int out_size)
{
    const float* hist = (const float*)d_in[0];
    const float* ques = (const float*)d_in[1];
    const float* Why  = (const float*)d_in[2];
    const float* bhy  = (const float*)d_in[3];
    const float* Whg  = (const float*)d_in[4];
    const float* bhg  = (const float*)d_in[5];
    const float* Wqy  = (const float*)d_in[6];
    const float* bqy  = (const float*)d_in[7];
    const float* Wqg  = (const float*)d_in[8];
    const float* bqg  = (const float*)d_in[9];
    const float* Watt = (const float*)d_in[10];
    const float* batt = (const float*)d_in[11];
    float* out = (float*)d_out;

    cudaFuncSetAttribute(embed_hmma_kernel,
                         cudaFuncAttributeMaxDynamicSharedMemorySize, EMB_SMEM);
    cudaFuncSetAttribute(feat_kernel,
                         cudaFuncAttributeMaxDynamicSharedMemorySize, FEAT_SMEM);

    conv_fused_kernel<<<6144, 256>>>(hist, ques, Why, Whg, Wqy, Wqg);
    embed_hmma_kernel<<<dim3(16, 32, 2), 256, EMB_SMEM>>>(bhy, bhg, bqy, bqg);
    score_hmma_kernel<<<dim3(KSL, B_), 128>>>(Watt);
    feat_kernel<<<dim3(IN_ / 256, B_), 256, FEAT_SMEM>>>(hist, batt, out);
}

// round 17
// speedup vs baseline: 1.0699x; 1.0335x over previous
#include <cuda_runtime.h>
#include <cuda_fp16.h>
#include <cstdint>
#include <math.h>

#define B_  64
#define R_  32
#define H_  1024
#define IN_ 2048
#define M_  (B_*R_)
#define KSL 8                 // score k-slices
#define KCH (H_/KSL)          // 128 k per slice

// ---------------- scratch (__device__ globals) -----------------------------
__device__ __align__(16) __half g_Ehf[2][M_][H_];          // embeds fp16
__device__ __align__(16) __half g_Xf[2][M_][IN_];          // X fp16 [M,K] ([0]=hist)
__device__ __align__(16) __half g_Wf[4][H_][IN_];          // W^T fp16 [N,K]
__device__ __align__(16) float  g_spart[KSL][B_][R_][R_];  // partial scores
__device__ __align__(16) float  g_npart[KSL][B_][R_][R_];  // partial norms

// ---------------- helpers --------------------------------------------------
__device__ __forceinline__ uint32_t smem_u32(const void* p){
    uint32_t a;
    asm("{ .reg .u64 t; cvta.to.shared.u64 t, %1; cvt.u32.u64 %0, t; }" : "=r"(a) : "l"(p));
    return a;
}
__device__ __forceinline__ void cpasync16(uint32_t dst, const void* src){
    asm volatile("cp.async.cg.shared.global [%0], [%1], 16;" :: "r"(dst), "l"(src));
}
#define CP_COMMIT() asm volatile("cp.async.commit_group;" ::: "memory")

#define LDSM_X4(d0,d1,d2,d3,addr) \
    asm volatile("ldmatrix.sync.aligned.m8n8.x4.shared.b16 {%0,%1,%2,%3}, [%4];" \
        : "=r"(d0),"=r"(d1),"=r"(d2),"=r"(d3) : "r"(addr))

#define LDSM_X4T(d0,d1,d2,d3,addr) \
    asm volatile("ldmatrix.sync.aligned.m8n8.x4.trans.shared.b16 {%0,%1,%2,%3}, [%4];" \
        : "=r"(d0),"=r"(d1),"=r"(d2),"=r"(d3) : "r"(addr))

#define MMA16816(c, a, b) \
    asm volatile("mma.sync.aligned.m16n8k16.row.col.f32.f16.f16.f32 " \
        "{%0,%1,%2,%3}, {%4,%5,%6,%7}, {%8,%9}, {%0,%1,%2,%3};" \
        : "+f"((c)[0]),"+f"((c)[1]),"+f"((c)[2]),"+f"((c)[3]) \
        : "r"((a)[0]),"r"((a)[1]),"r"((a)[2]),"r"((a)[3]), "r"((b)[0]),"r"((b)[1]))

__device__ __forceinline__ uint32_t sqr_h2(uint32_t x){
    __half2 h = *reinterpret_cast<__half2*>(&x);
    __half2 r = __hmul2(h, h);
    return *reinterpret_cast<uint32_t*>(&r);
}

// ---------------------------------------------------------------------------
// fused conv: part 1 (X fp32->fp16), part 2 (W transpose fp32->fp16 [N,K])
// ---------------------------------------------------------------------------
__global__ __launch_bounds__(256)
void conv_fused_kernel(const float* __restrict__ hist, const float* __restrict__ ques,
                       const float* __restrict__ W0, const float* __restrict__ W1,
                       const float* __restrict__ W2, const float* __restrict__ W3)
{
    const int bx = blockIdx.x;
    const int tid = threadIdx.x;
    if (bx < 4096){
        const int z = bx >> 11;
        const int xb = bx & 2047;
        const float* X = z ? ques : hist;
        __half* dst = &g_Xf[z][0][0];
        size_t i = ((size_t)xb * 256 + tid) * 8;
        float4 v0 = *(const float4*)(X + i);
        float4 v1 = *(const float4*)(X + i + 4);
        __half2 h[4];
        h[0] = __floats2half2_rn(v0.x, v0.y);
        h[1] = __floats2half2_rn(v0.z, v0.w);
        h[2] = __floats2half2_rn(v1.x, v1.y);
        h[3] = __floats2half2_rn(v1.z, v1.w);
        *(uint4*)(dst + i) = *(uint4*)h;
    } else {
        const float* Ws[4] = {W0, W1, W2, W3};
        const int wb  = bx - 4096;
        const int br  = wb >> 9;
        const int rem = wb & 511;
        const int n0  = (rem >> 5) * 64;
        const int k0  = (rem & 31) * 64;
        const float* W = Ws[br];
        __shared__ float s[64][65];
        #pragma unroll
        for (int i = 0; i < 4; i++){
            int idx = tid + i * 256;
            int r = idx >> 4;
            int c = (idx & 15) * 4;
            float4 v = *(const float4*)(W + (size_t)(k0 + r) * H_ + n0 + c);
            s[r][c] = v.x; s[r][c+1] = v.y; s[r][c+2] = v.z; s[r][c+3] = v.w;
        }
        __syncthreads();
        int nl  = tid >> 2;
        int seg = (tid & 3) * 16;
        __half2 h[8];
        #pragma unroll
        for (int j = 0; j < 8; j++)
            h[j] = __floats2half2_rn(s[seg + 2*j][nl], s[seg + 2*j + 1][nl]);
        __half* o = &g_Wf[br][n0 + nl][k0 + seg];
        *(uint4*)(o)     = *(uint4*)&h[0];
        *(uint4*)(o + 8) = *(uint4*)&h[4];
    }
}

// ---------------------------------------------------------------------------
// embed GEMM: HMMA m16n8k16 fp16, dual-branch, 3-stage cp.async, BK=64,
// one __syncthreads per K-iter. grid (16, 32, 2) = 1024 CTAs.
// ---------------------------------------------------------------------------
#define PITCH  72
#define ST_A   (128 * PITCH * 2)
#define ST_Bb  (32 * PITCH * 2)
#define ST_TOT (ST_A + 2 * ST_Bb)
#define EMB_SMEM (3 * ST_TOT)

__global__ __launch_bounds__(256, 2)
void embed_hmma_kernel(const float* __restrict__ bhy, const float* __restrict__ bhg,
                       const float* __restrict__ bqy, const float* __restrict__ bqg)
{
    extern __shared__ __align__(16) char sm[];
    const uint32_t smu = smem_u32(sm);

    const int tid  = threadIdx.x;
    const int lane = tid & 31, wid = tid >> 5;
    const int wm = wid >> 1, wn = wid & 1;
    const int z  = blockIdx.z;
    const int m0 = blockIdx.x * 128;
    const int n0 = blockIdx.y * 32;

    const __half* Xf = &g_Xf[z][0][0];
    const __half* Wy = &g_Wf[2*z + 0][0][0];
    const __half* Wg = &g_Wf[2*z + 1][0][0];

    float acc[2][2][2][4];
    #pragma unroll
    for (int b = 0; b < 2; b++)
        #pragma unroll
        for (int mi = 0; mi < 2; mi++)
            #pragma unroll
            for (int ni = 0; ni < 2; ni++)
                #pragma unroll
                for (int r = 0; r < 4; r++) acc[b][mi][ni][r] = 0.f;

    auto load_stage = [&](int s){
        const int k0 = s * 64, buf = s % 3;
        const uint32_t base = smu + buf * ST_TOT;
        #pragma unroll
        for (int i = 0; i < 4; i++){
            int idx = tid + i * 256;
            int row = idx >> 3, seg = idx & 7;
            cpasync16(base + (row * PITCH + seg * 8) * 2,
                      Xf + (size_t)(m0 + row) * IN_ + k0 + seg * 8);
        }
        #pragma unroll
        for (int i = 0; i < 2; i++){
            int idx = tid + i * 256;
            int t = idx >> 8, r = (idx >> 3) & 31, seg = idx & 7;
            const __half* W = t ? Wg : Wy;
            cpasync16(base + ST_A + t * ST_Bb + (r * PITCH + seg * 8) * 2,
                      W + (size_t)(n0 + r) * IN_ + k0 + seg * 8);
        }
    };

    load_stage(0); CP_COMMIT();
    load_stage(1); CP_COMMIT();

    const int lr = lane & 15;
    const int lc = (lane >> 4) * 8;

    for (int s = 0; s < 32; s++){
        if (s < 31) asm volatile("cp.async.wait_group 1;" ::: "memory");
        else        asm volatile("cp.async.wait_group 0;" ::: "memory");
        __syncthreads();
        if (s + 2 < 32){ load_stage(s + 2); CP_COMMIT(); }

        const uint32_t base  = smu + (s % 3) * ST_TOT;
        const uint32_t bBase = base + ST_A;

        #pragma unroll
        for (int kk = 0; kk < 64; kk += 16){
            uint32_t a[2][4];
            #pragma unroll
            for (int mi = 0; mi < 2; mi++){
                uint32_t ad = base + ((wm*32 + mi*16 + lr) * PITCH + kk + lc) * 2;
                LDSM_X4(a[mi][0], a[mi][1], a[mi][2], a[mi][3], ad);
            }
            #pragma unroll
            for (int br = 0; br < 2; br++){
                uint32_t t0, t1, t2, t3;
                uint32_t bd = bBase + br * ST_Bb +
                              ((wn*16 + lr) * PITCH + kk + lc) * 2;
                LDSM_X4(t0, t1, t2, t3, bd);
                uint32_t b0[2] = {t0, t2};
                uint32_t b1[2] = {t1, t3};
                #pragma unroll
                for (int mi = 0; mi < 2; mi++){
                    MMA16816(acc[br][mi][0], a[mi], b0);
                    MMA16816(acc[br][mi][1], a[mi], b1);
                }
            }
        }
    }

    const float* by = z ? bqy : bhy;
    const float* bg = z ? bqg : bhg;
    const int grp = lane >> 2, tig = lane & 3;
    #pragma unroll
    for (int mi = 0; mi < 2; mi++){
        #pragma unroll
        for (int ni = 0; ni < 2; ni++){
            const float* ay = acc[0][mi][ni];
            const float* ag = acc[1][mi][ni];
            const int gn  = n0 + wn*16 + ni*8 + tig*2;
            const int gm0 = m0 + wm*32 + mi*16 + grp;
            const float by0 = by[gn], by1 = by[gn+1];
            const float bg0 = bg[gn], bg1 = bg[gn+1];
            float g0 = ag[0] + bg0; g0 = g0 > 0.f ? g0 : 0.01f * g0;
            float g1 = ag[1] + bg1; g1 = g1 > 0.f ? g1 : 0.01f * g1;
            float g2 = ag[2] + bg0; g2 = g2 > 0.f ? g2 : 0.01f * g2;
            float g3 = ag[3] + bg1; g3 = g3 > 0.f ? g3 : 0.01f * g3;
            __half2 o0 = __floats2half2_rn(tanhf(ay[0] + by0) * g0,
                                           tanhf(ay[1] + by1) * g1);
            __half2 o1 = __floats2half2_rn(tanhf(ay[2] + by0) * g2,
                                           tanhf(ay[3] + by1) * g3);
            *(__half2*)&g_Ehf[z][gm0    ][gn] = o0;
            *(__half2*)&g_Ehf[z][gm0 + 8][gn] = o1;
        }
    }
}

// ---------------------------------------------------------------------------
// score via HMMA: S = Eq @ (Eh.w)^T, N = Eq^2 @ (Eh^2)^T, split-K (KSL, B_).
// ---------------------------------------------------------------------------
#define SPITCH 136

__global__ __launch_bounds__(128)
void score_hmma_kernel(const float* __restrict__ W_att)
{
    __shared__ __align__(16) __half sq [32 * SPITCH];
    __shared__ __align__(16) __half shh[32 * SPITCH];
    __shared__ __align__(16) __half shw[32 * SPITCH];

    const int sl = blockIdx.x;
    const int b  = blockIdx.y;
    const int kb = sl * KCH;
    const int tid = threadIdx.x, lane = tid & 31, w = tid >> 5;

    #pragma unroll
    for (int i = 0; i < 4; i++){
        int idx = tid + i * 128;
        int r   = idx >> 4;
        int seg = idx & 15;
        uint4 vq = *(const uint4*)&g_Ehf[1][b*R_ + r][kb + seg*8];
        *(uint4*)&sq[r * SPITCH + seg*8] = vq;
        uint4 vh = *(const uint4*)&g_Ehf[0][b*R_ + r][kb + seg*8];
        *(uint4*)&shh[r * SPITCH + seg*8] = vh;
        const float* wp = W_att + kb + seg*8;
        float4 w0 = *(const float4*)wp;
        float4 w1 = *(const float4*)(wp + 4);
        const __half* h8 = (const __half*)&vh;
        __half o8[8];
        o8[0] = __float2half_rn(__half2float(h8[0]) * w0.x);
        o8[1] = __float2half_rn(__half2float(h8[1]) * w0.y);
        o8[2] = __float2half_rn(__half2float(h8[2]) * w0.z);
        o8[3] = __float2half_rn(__half2float(h8[3]) * w0.w);
        o8[4] = __float2half_rn(__half2float(h8[4]) * w1.x);
        o8[5] = __float2half_rn(__half2float(h8[5]) * w1.y);
        o8[6] = __float2half_rn(__half2float(h8[6]) * w1.z);
        o8[7] = __float2half_rn(__half2float(h8[7]) * w1.w);
        *(uint4*)&shw[r * SPITCH + seg*8] = *(uint4*)o8;
    }
    __syncthreads();

    const int wm = w & 1, wn = w >> 1;
    const int lr = lane & 15, lc = (lane >> 4) * 8;
    const uint32_t aB = smem_u32(sq);
    const uint32_t hB = smem_u32(shh);
    const uint32_t wB = smem_u32(shw);

    float cs[2][4] = {{0,0,0,0},{0,0,0,0}};
    float cn[2][4] = {{0,0,0,0},{0,0,0,0}};

    #pragma unroll
    for (int kk = 0; kk < KCH; kk += 16){
        uint32_t a[4], a2[4];
        LDSM_X4(a[0], a[1], a[2], a[3], aB + ((wm*16 + lr) * SPITCH + kk + lc) * 2);
        #pragma unroll
        for (int i = 0; i < 4; i++) a2[i] = sqr_h2(a[i]);

        uint32_t tw0, tw1, tw2, tw3;
        LDSM_X4(tw0, tw1, tw2, tw3, wB + ((wn*16 + lr) * SPITCH + kk + lc) * 2);
        uint32_t th0, th1, th2, th3;
        LDSM_X4(th0, th1, th2, th3, hB + ((wn*16 + lr) * SPITCH + kk + lc) * 2);

        uint32_t bS0[2] = {tw0, tw2}, bS1[2] = {tw1, tw3};
        uint32_t b20[2] = {sqr_h2(th0), sqr_h2(th2)};
        uint32_t b21[2] = {sqr_h2(th1), sqr_h2(th3)};

        MMA16816(cs[0], a, bS0);
        MMA16816(cs[1], a, bS1);
        MMA16816(cn[0], a2, b20);
        MMA16816(cn[1], a2, b21);
    }

    const int grp = lane >> 2, tig = lane & 3;
    const int q0 = wm * 16 + grp;
    #pragma unroll
    for (int t = 0; t < 2; t++){
        const int hc = wn * 16 + t * 8 + tig * 2;
        *(float2*)&g_spart[sl][b][q0    ][hc] = make_float2(cs[t][0], cs[t][1]);
        *(float2*)&g_spart[sl][b][q0 + 8][hc] = make_float2(cs[t][2], cs[t][3]);
        *(float2*)&g_npart[sl][b][q0    ][hc] = make_float2(cn[t][0], cn[t][1]);
        *(float2*)&g_npart[sl][b][q0 + 8][hc] = make_float2(cn[t][2], cn[t][3]);
    }
}

// ---------------------------------------------------------------------------
// feat via HMMA (+ fused combine/softmax): grid (IN_/256, B_) = 512 blocks.
// feat[q,d] = sum_h att[q,h] * hist_f16[h,d]  -> m16n8k16, fp32 accum.
// A: att fp16 [32q x 32h] smem (pitch 40). B: hist fp16 [32h x 256d] smem
// (pitch 264), fragments via ldmatrix.x4.trans. 8 warps = 2 m x 4 d-groups.
// ---------------------------------------------------------------------------
#define APITCH 40
#define HPITCH 264

__global__ __launch_bounds__(256)
void feat_kernel(const float* __restrict__ b_att_p, float* __restrict__ out)
{
    __shared__ __align__(16) __half s_att[32 * APITCH];
    __shared__ __align__(16) __half s_hist[32 * HPITCH];

    const int b   = blockIdx.y;
    const int d0  = blockIdx.x * 256;
    const int tid = threadIdx.x;
    const int lane = tid & 31, w = tid >> 5;

    // Phase 1: combine + masked softmax -> fp16 att (warp w -> q rows w*4+j)
    #pragma unroll
    for (int j = 0; j < 4; j++){
        const int q = w * 4 + j;
        const int h = lane;
        float s = 0.f, n = 0.f;
        #pragma unroll
        for (int sl = 0; sl < KSL; sl++){
            s += g_spart[sl][b][q][h];
            n += g_npart[sl][b][q][h];
        }
        float x = s / fmaxf(sqrtf(n), 1e-12f) + b_att_p[0];
        bool valid = (h <= q);
        float xm = valid ? x : -1e30f;
        #pragma unroll
        for (int off = 16; off; off >>= 1)
            xm = fmaxf(xm, __shfl_xor_sync(0xffffffffu, xm, off));
        float e = valid ? expf(x - xm) : 0.f;
        float se = e;
        #pragma unroll
        for (int off = 16; off; off >>= 1)
            se += __shfl_xor_sync(0xffffffffu, se, off);
        s_att[q * APITCH + h] = __float2half_rn(e / se);
    }

    // Phase 2: hist fp16 tile [32h x 256d] -> smem (1024 chunks of 8 halves)
    #pragma unroll
    for (int i = 0; i < 4; i++){
        int idx = tid + i * 256;          // 0..1023
        int h   = idx >> 5;               // 0..31
        int c   = (idx & 31) * 8;         // 0..248
        *(uint4*)&s_hist[h * HPITCH + c] =
            *(const uint4*)&g_Xf[0][b * R_ + h][d0 + c];
    }
    __syncthreads();

    const int wqm = w & 1;                // m-tile (q 0-15 / 16-31)
    const int wdn = w >> 1;               // d-group of 64
    const int lr = lane & 15, lc = (lane >> 4) * 8;
    const uint32_t aB = smem_u32(s_att);
    const uint32_t hB = smem_u32(s_hist);

    float acc[8][4];
    #pragma unroll
    for (int g = 0; g < 8; g++)
        #pragma unroll
        for (int r = 0; r < 4; r++) acc[g][r] = 0.f;

    #pragma unroll
    for (int ks = 0; ks < 32; ks += 16){
        uint32_t a[4];
        LDSM_X4(a[0], a[1], a[2], a[3],
                aB + ((wqm*16 + lr) * APITCH + ks + lc) * 2);
        #pragma unroll
        for (int ni = 0; ni < 4; ni++){
            uint32_t r0, r1, r2, r3;
            LDSM_X4T(r0, r1, r2, r3,
                     hB + ((ks + lr) * HPITCH + wdn*64 + ni*16 + lc) * 2);
            uint32_t b0[2] = {r0, r1};
            uint32_t b1[2] = {r2, r3};
            MMA16816(acc[ni*2    ], a, b0);
            MMA16816(acc[ni*2 + 1], a, b1);
        }
    }

    const int grp = lane >> 2, tig = lane & 3;
    const int q0 = wqm * 16 + grp;
    float* ob = out + (size_t)(b * R_) * IN_ + d0 + wdn * 64;
    #pragma unroll
    for (int g = 0; g < 8; g++){
        const int dc = g * 8 + tig * 2;
        *(float2*)&ob[(size_t)(q0    ) * IN_ + dc] = make_float2(acc[g][0], acc[g][1]);
        *(float2*)&ob[(size_t)(q0 + 8) * IN_ + dc] = make_float2(acc[g][2], acc[g][3]);
    }
}

// ---------------------------------------------------------------------------
extern "C" void kernel_launch(void* const* d_in, const int* in_sizes, int n_in,
                              void* d_out, int out_size)
{
    const float* hist = (const float*)d_in[0];
    const float* ques = (const float*)d_in[1];
    const float* Why  = (const float*)d_in[2];
    const float* bhy  = (const float*)d_in[3];
    const float* Whg  = (const float*)d_in[4];
    const float* bhg  = (const float*)d_in[5];
    const float* Wqy  = (const float*)d_in[6];
    const float* bqy  = (const float*)d_in[7];
    const float* Wqg  = (const float*)d_in[8];
    const float* bqg  = (const float*)d_in[9];
    const float* Watt = (const float*)d_in[10];
    const float* batt = (const float*)d_in[11];
    float* out = (float*)d_out;

    cudaFuncSetAttribute(embed_hmma_kernel,
                         cudaFuncAttributeMaxDynamicSharedMemorySize, EMB_SMEM);

    conv_fused_kernel<<<6144, 256>>>(hist, ques, Why, Whg, Wqy, Wqg);
    embed_hmma_kernel<<<dim3(16, 32, 2), 256, EMB_SMEM>>>(bhy, bhg, bqy, bqg);
    score_hmma_kernel<<<dim3(KSL, B_), 128>>>(Watt);
    feat_kernel<<<dim3(IN_ / 256, B_), 256>>>(batt, out);
}